// round 1
// baseline (speedup 1.0000x reference)
#include <cuda_runtime.h>
#include <cuda_bf16.h>

// Problem constants (fixed by the dataset)
#define T_ 2048
#define B_ 64
#define H_ 128
#define G_ 384          // 3*H
#define C_ 32
#define M_ (T_ * B_)    // 131072 rows

// ---------------- scratch (device globals; no allocation allowed) ----------
__device__ float g_gi[(size_t)M_ * G_];     // input gates, [T, B, 384] (reused by both layers)
__device__ float g_hseq[(size_t)M_ * H_];   // layer-0 output, [T, B, 128]
__device__ float g_y[(size_t)M_ * H_];      // layer-1 output, [B, T, 128]

// ---------------- helpers ---------------------------------------------------
static __device__ __forceinline__ unsigned long long pk2(float a, float b) {
    unsigned long long r;
    asm("mov.b64 %0, {%1,%2};" : "=l"(r) : "f"(a), "f"(b));
    return r;
}
static __device__ __forceinline__ void upk2(unsigned long long v, float& a, float& b) {
    asm("mov.b64 {%0,%1}, %2;" : "=f"(a), "=f"(b) : "l"(v));
}
// packed fp32x2 FMA (Blackwell): 2x FFMA throughput
static __device__ __forceinline__ unsigned long long fma2(
    unsigned long long a, unsigned long long b, unsigned long long c) {
    unsigned long long d;
    asm("fma.rn.f32x2 %0, %1, %2, %3;" : "=l"(d) : "l"(a), "l"(b), "l"(c));
    return d;
}
static __device__ __forceinline__ float sigm(float x) {
    return 1.0f / (1.0f + __expf(-x));   // expf(-x) overflow -> inf -> 0, correct limit
}
static __device__ __forceinline__ float tanh_fast(float x) {
    x = fminf(15.0f, fmaxf(-15.0f, x));
    float e = __expf(2.0f * x);
    return __fdividef(e - 1.0f, e + 1.0f);
}

// ---------------- GEMM: C[M,384] = A[M,128] @ W[384,128]^T + bias ----------
// A rows either direct (Asrc) or gathered from emb[x] (gather=1).
// Output row m corresponds to (t = m/B, b = m%B); x is [B,T].
__global__ __launch_bounds__(256) void gemm_k128(
    const float* __restrict__ Asrc,
    const int*   __restrict__ x,
    const float* __restrict__ emb,
    const float* __restrict__ W,
    const float* __restrict__ bias,
    float*       __restrict__ C,
    int gather)
{
    __shared__ float At[64][65];   // k-major A tile (transposed)
    __shared__ float Wt[64][65];   // k-major W tile (transposed)

    const int bm = blockIdx.y * 64;
    const int bn = blockIdx.x * 64;
    const int tid = threadIdx.x;
    const int tx = tid & 15;       // col group (4 cols)
    const int ty = tid >> 4;       // row group (4 rows)

    float acc[4][4];
#pragma unroll
    for (int i = 0; i < 4; i++)
#pragma unroll
        for (int j = 0; j < 4; j++) acc[i][j] = 0.0f;

    for (int k0 = 0; k0 < 128; k0 += 64) {
        // Load A tile (64 rows x 64 k) -> At[kk][row]
#pragma unroll
        for (int j = 0; j < 4; j++) {
            int f   = tid + j * 256;      // 0..1023 float4 slots (64 rows x 16 f4)
            int row = f >> 4;
            int kq  = f & 15;
            const float* src;
            if (gather) {
                int m  = bm + row;
                int bb = m & (B_ - 1);
                int tt = m >> 6;
                src = emb + (size_t)x[bb * T_ + tt] * 128;
            } else {
                src = Asrc + (size_t)(bm + row) * 128;
            }
            float4 v = *(const float4*)(src + k0 + kq * 4);
            At[kq * 4 + 0][row] = v.x;
            At[kq * 4 + 1][row] = v.y;
            At[kq * 4 + 2][row] = v.z;
            At[kq * 4 + 3][row] = v.w;
        }
        // Load W tile (64 n-rows x 64 k) -> Wt[kk][n]
#pragma unroll
        for (int j = 0; j < 4; j++) {
            int f   = tid + j * 256;
            int row = f >> 4;
            int kq  = f & 15;
            const float* src = W + (size_t)(bn + row) * 128;
            float4 v = *(const float4*)(src + k0 + kq * 4);
            Wt[kq * 4 + 0][row] = v.x;
            Wt[kq * 4 + 1][row] = v.y;
            Wt[kq * 4 + 2][row] = v.z;
            Wt[kq * 4 + 3][row] = v.w;
        }
        __syncthreads();

#pragma unroll
        for (int k = 0; k < 64; k++) {
            float a[4], w[4];
#pragma unroll
            for (int i = 0; i < 4; i++) a[i] = At[k][ty * 4 + i];
#pragma unroll
            for (int i = 0; i < 4; i++) w[i] = Wt[k][tx * 4 + i];
#pragma unroll
            for (int i = 0; i < 4; i++)
#pragma unroll
                for (int j = 0; j < 4; j++) acc[i][j] += a[i] * w[j];
        }
        __syncthreads();
    }

#pragma unroll
    for (int i = 0; i < 4; i++) {
        int m = bm + ty * 4 + i;
#pragma unroll
        for (int j = 0; j < 4; j++) {
            int n = bn + tx * 4 + j;
            C[(size_t)m * G_ + n] = acc[i][j] + bias[n];
        }
    }
}

// ---------------- sequential GRU scan: one CTA per batch element -----------
// gi: [T, B, 384]  (r | z | n gate order, bias b_ih already added)
// whh: [384, 128], bhh: [384]
// out[t*os_t + b*os_b + j] = h_t[j]
__global__ __launch_bounds__(384, 1) void gru_scan(
    const float* __restrict__ gi,
    const float* __restrict__ whh,
    const float* __restrict__ bhh,
    float*       __restrict__ out,
    long os_t, long os_b)
{
    __shared__ __align__(16) float h_sh[H_];
    __shared__ float gh_sh[G_];

    const int b = blockIdx.x;
    const int g = threadIdx.x;       // 0..383: gate row owned by this thread

    // Load this thread's 128 W_hh weights into registers as 64 f32x2 pairs.
    unsigned long long w2[64];
    {
        const float4* wrow = (const float4*)(whh + (size_t)g * H_);
#pragma unroll
        for (int i = 0; i < 32; i++) {
            float4 v = wrow[i];
            w2[2 * i + 0] = pk2(v.x, v.y);
            w2[2 * i + 1] = pk2(v.z, v.w);
        }
    }
    const float bias = bhh[g];

    if (g < H_) h_sh[g] = 0.0f;

    // preload gi for t=0 (threads g<128 hold the 3 gate inputs for row g)
    float gi_r = 0.f, gi_z = 0.f, gi_n = 0.f;
    if (g < H_) {
        const float* p = gi + (size_t)b * G_;
        gi_r = p[g];
        gi_z = p[g + H_];
        gi_n = p[g + 2 * H_];
    }
    __syncthreads();

    for (int t = 0; t < T_; t++) {
        // prefetch next step's gi (covers DRAM latency under the dot product)
        float nr = 0.f, nz = 0.f, nn = 0.f;
        if (g < H_ && t + 1 < T_) {
            const float* p = gi + ((size_t)(t + 1) * B_ + b) * G_;
            nr = p[g];
            nz = p[g + H_];
            nn = p[g + 2 * H_];
        }

        // gh[g] = bhh[g] + W_hh[g,:] . h   (packed fp32x2, weights in regs)
        unsigned long long acc0 = pk2(bias, 0.0f);
        unsigned long long acc1 = pk2(0.0f, 0.0f);
        const ulonglong2* hq = (const ulonglong2*)h_sh;
#pragma unroll
        for (int i = 0; i < 32; i++) {
            ulonglong2 hv = hq[i];                 // broadcast LDS.128
            acc0 = fma2(w2[2 * i + 0], hv.x, acc0);
            acc1 = fma2(w2[2 * i + 1], hv.y, acc1);
        }
        float a0, a1, a2, a3;
        upk2(acc0, a0, a1);
        upk2(acc1, a2, a3);
        gh_sh[g] = (a0 + a2) + (a1 + a3);
        __syncthreads();   // gh visible; also: all h_sh reads of this step done

        if (g < H_) {
            float r  = sigm(gi_r + gh_sh[g]);
            float z  = sigm(gi_z + gh_sh[g + H_]);
            float n  = tanh_fast(gi_n + r * gh_sh[g + 2 * H_]);
            float hn = (1.0f - z) * n + z * h_sh[g];
            h_sh[g] = hn;
            out[(long)t * os_t + (long)b * os_b + g] = hn;
            gi_r = nr; gi_z = nz; gi_n = nn;
        }
        __syncthreads();   // new h visible to all before next dot product
    }
}

// ---------------- FC: out[M,32] = relu(Y[M,128] @ fcw[32,128]^T + fcb) -----
__global__ __launch_bounds__(256) void fc_kernel(
    const float* __restrict__ Y,
    const float* __restrict__ fcw,
    const float* __restrict__ fcb,
    float*       __restrict__ out)
{
    __shared__ float Wt[128][33];   // k-major fc weights
    __shared__ float As[128][33];   // k-major A rows (32 rows)

    const int bm  = blockIdx.x * 32;
    const int tid = threadIdx.x;

    // load fcw [32][128] -> Wt[k][c]
#pragma unroll
    for (int j = 0; j < 4; j++) {
        int f  = tid + j * 256;      // 0..1023 (32 rows x 32 f4)
        int c  = f >> 5;
        int kq = f & 31;
        float4 v = *(const float4*)(fcw + (size_t)c * 128 + kq * 4);
        Wt[kq * 4 + 0][c] = v.x;
        Wt[kq * 4 + 1][c] = v.y;
        Wt[kq * 4 + 2][c] = v.z;
        Wt[kq * 4 + 3][c] = v.w;
    }
    // load 32 A rows -> As[k][r]
#pragma unroll
    for (int j = 0; j < 4; j++) {
        int f  = tid + j * 256;
        int r  = f >> 5;
        int kq = f & 31;
        float4 v = *(const float4*)(Y + (size_t)(bm + r) * 128 + kq * 4);
        As[kq * 4 + 0][r] = v.x;
        As[kq * 4 + 1][r] = v.y;
        As[kq * 4 + 2][r] = v.z;
        As[kq * 4 + 3][r] = v.w;
    }
    __syncthreads();

    const int c  = tid & 31;        // output column
    const int rg = tid >> 5;        // row group: rows rg*4 .. rg*4+3
    float acc[4] = {0.f, 0.f, 0.f, 0.f};
#pragma unroll
    for (int k = 0; k < 128; k++) {
        float w = Wt[k][c];
#pragma unroll
        for (int i = 0; i < 4; i++) acc[i] += As[k][rg * 4 + i] * w;
    }
    float bb = fcb[c];
#pragma unroll
    for (int i = 0; i < 4; i++) {
        float v = acc[i] + bb;
        out[(size_t)(bm + rg * 4 + i) * C_ + c] = fmaxf(v, 0.0f);
    }
}

// ---------------- launch ----------------------------------------------------
extern "C" void kernel_launch(void* const* d_in, const int* in_sizes, int n_in,
                              void* d_out, int out_size)
{
    const int*   x    = (const int*)  d_in[0];
    const float* emb  = (const float*)d_in[1];
    const float* wih0 = (const float*)d_in[2];
    const float* whh0 = (const float*)d_in[3];
    const float* bih0 = (const float*)d_in[4];
    const float* bhh0 = (const float*)d_in[5];
    const float* wih1 = (const float*)d_in[6];
    const float* whh1 = (const float*)d_in[7];
    const float* bih1 = (const float*)d_in[8];
    const float* bhh1 = (const float*)d_in[9];
    const float* fcw  = (const float*)d_in[10];
    const float* fcb  = (const float*)d_in[11];
    float* out = (float*)d_out;

    void* p;
    cudaGetSymbolAddress(&p, g_gi);   float* gi   = (float*)p;
    cudaGetSymbolAddress(&p, g_hseq); float* hseq = (float*)p;
    cudaGetSymbolAddress(&p, g_y);    float* y    = (float*)p;

    dim3 ggrid(G_ / 64, M_ / 64);   // (6, 2048)

    // 1) gi0 = gather(emb, x) @ w_ih0^T + b_ih0       [T,B,384]
    gemm_k128<<<ggrid, 256>>>(nullptr, x, emb, wih0, bih0, gi, 1);

    // 2) layer-0 scan -> hseq [T,B,128]
    gru_scan<<<B_, 384>>>(gi, whh0, bhh0, hseq, (long)B_ * H_, (long)H_);

    // 3) gi1 = hseq @ w_ih1^T + b_ih1                 [T,B,384] (reuse buffer)
    gemm_k128<<<ggrid, 256>>>(hseq, nullptr, nullptr, wih1, bih1, gi, 0);

    // 4) layer-1 scan -> y [B,T,128] (FC-friendly layout)
    gru_scan<<<B_, 384>>>(gi, whh1, bhh1, y, (long)H_, (long)T_ * H_);

    // 5) out = relu(y @ fc_w^T + fc_b)                [B*T, 32]
    fc_kernel<<<M_ / 32, 256>>>(y, fcw, fcb, out);
}

// round 3
// speedup vs baseline: 1.0436x; 1.0436x over previous
#include <cuda_runtime.h>
#include <cuda_bf16.h>
#include <mma.h>
#include <cstdint>

using namespace nvcuda;

// Problem constants (fixed by the dataset)
#define T_ 2048
#define B_ 64
#define H_ 128
#define G_ 384          // 3*H
#define C_ 32
#define M_ (T_ * B_)    // 131072 rows
#define V_ 50257

// ---------------- scratch (device globals; no allocation allowed) ----------
__device__ float g_gi[(size_t)M_ * G_];            // input gates, [T, B, 384] (no b_ih)
__device__ float g_y[(size_t)M_ * H_];             // layer-1 output, [B, T, 128]
__device__ __nv_bfloat16 g_hseq_hi[(size_t)M_ * H_];   // layer-0 out hi, [T,B,128]
__device__ __nv_bfloat16 g_hseq_lo[(size_t)M_ * H_];   // layer-0 out lo
__device__ __nv_bfloat16 g_emb_hi[(size_t)V_ * H_];
__device__ __nv_bfloat16 g_emb_lo[(size_t)V_ * H_];
__device__ __nv_bfloat16 g_w0_hi[G_ * H_];
__device__ __nv_bfloat16 g_w0_lo[G_ * H_];
__device__ __nv_bfloat16 g_w1_hi[G_ * H_];
__device__ __nv_bfloat16 g_w1_lo[G_ * H_];

// ---------------- helpers ---------------------------------------------------
static __device__ __forceinline__ unsigned long long pk2(float a, float b) {
    unsigned long long r;
    asm("mov.b64 %0, {%1,%2};" : "=l"(r) : "f"(a), "f"(b));
    return r;
}
static __device__ __forceinline__ void upk2(unsigned long long v, float& a, float& b) {
    asm("mov.b64 {%0,%1}, %2;" : "=f"(a), "=f"(b) : "l"(v));
}
// packed fp32x2 FMA (Blackwell): 2x FFMA throughput
static __device__ __forceinline__ unsigned long long fma2(
    unsigned long long a, unsigned long long b, unsigned long long c) {
    unsigned long long d;
    asm("fma.rn.f32x2 %0, %1, %2, %3;" : "=l"(d) : "l"(a), "l"(b), "l"(c));
    return d;
}
static __device__ __forceinline__ float sigm(float x) {
    return 1.0f / (1.0f + __expf(-x));
}
static __device__ __forceinline__ float tanh_fast(float x) {
    x = fminf(15.0f, fmaxf(-15.0f, x));
    float e = __expf(2.0f * x);
    return __fdividef(e - 1.0f, e + 1.0f);
}

// ---------------- fp32 -> bf16 hi/lo split conversion ----------------------
__global__ __launch_bounds__(256) void convert_kernel(
    const float* __restrict__ emb, const float* __restrict__ w0,
    const float* __restrict__ w1)
{
    long i = (long)blockIdx.x * 256 + threadIdx.x;
    const long NE = (long)V_ * H_;
    const long NW = (long)G_ * H_;
    if (i < NE) {
        float v = emb[i];
        __nv_bfloat16 h = __float2bfloat16(v);
        g_emb_hi[i] = h;
        g_emb_lo[i] = __float2bfloat16(v - __bfloat162float(h));
        return;
    }
    long j = i - NE;
    if (j < NW) {
        float v = w0[j];
        __nv_bfloat16 h = __float2bfloat16(v);
        g_w0_hi[j] = h;
        g_w0_lo[j] = __float2bfloat16(v - __bfloat162float(h));
        return;
    }
    j -= NW;
    if (j < NW) {
        float v = w1[j];
        __nv_bfloat16 h = __float2bfloat16(v);
        g_w1_hi[j] = h;
        g_w1_lo[j] = __float2bfloat16(v - __bfloat162float(h));
    }
}

// ---------------- WMMA GEMM: C[M,384] = A[M,128] @ W[384,128]^T ------------
// A given as bf16 hi/lo (gathered via token ids, or direct rows).
// CTA tile 128(M) x 128(N), K=128, 8 warps as 2(M) x 4(N); warp tile 64x32.
// hi/lo split: acc += Ah*Wh + Ah*Wl + Al*Wh  (fp32 accumulate).
#define LDM 136                      // padded leading dim (bf16 elems)
#define TILE_B (128 * LDM * 2)       // bytes per bf16 tile (34816)
#define SM_TOT (4 * TILE_B)          // Ahi, Alo, Whi, Wlo

__global__ __launch_bounds__(256, 1) void gemm_wmma(
    const int*           __restrict__ x,      // tokens [B,T] (gather mode)
    const __nv_bfloat16* __restrict__ a_hi,
    const __nv_bfloat16* __restrict__ a_lo,
    const __nv_bfloat16* __restrict__ w_hi,
    const __nv_bfloat16* __restrict__ w_lo,
    float*               __restrict__ Cout,
    int gather)
{
    extern __shared__ __align__(16) char smem[];
    __nv_bfloat16* Ahi = (__nv_bfloat16*)(smem);
    __nv_bfloat16* Alo = (__nv_bfloat16*)(smem + TILE_B);
    __nv_bfloat16* Whi = (__nv_bfloat16*)(smem + 2 * TILE_B);
    __nv_bfloat16* Wlo = (__nv_bfloat16*)(smem + 3 * TILE_B);

    const int tid = threadIdx.x;
    const int bn  = blockIdx.x * 128;
    const int bm  = blockIdx.y * 128;

    // Stage all four 128x128 bf16 tiles. Each row = 256B = 16 uint4 chunks.
    // 2048 chunks per tile; 256 threads -> 8 iterations per tile.
#pragma unroll
    for (int it = 0; it < 8; it++) {
        int i   = tid + it * 256;           // 0..2047
        int row = i >> 4;
        int ch  = (i & 15);                 // 16B chunk index in row
        const char *pah, *pal;
        if (gather) {
            int m = bm + row;
            int token = x[(m & (B_ - 1)) * T_ + (m >> 6)];
            pah = (const char*)(a_hi + (size_t)token * H_);
            pal = (const char*)(a_lo + (size_t)token * H_);
        } else {
            pah = (const char*)(a_hi + (size_t)(bm + row) * H_);
            pal = (const char*)(a_lo + (size_t)(bm + row) * H_);
        }
        const char* pwh = (const char*)(w_hi + (size_t)(bn + row) * H_);
        const char* pwl = (const char*)(w_lo + (size_t)(bn + row) * H_);
        size_t doff = (size_t)row * LDM + ch * 8;   // elem offset in smem tile
        *(uint4*)(Ahi + doff) = *(const uint4*)(pah + ch * 16);
        *(uint4*)(Alo + doff) = *(const uint4*)(pal + ch * 16);
        *(uint4*)(Whi + doff) = *(const uint4*)(pwh + ch * 16);
        *(uint4*)(Wlo + doff) = *(const uint4*)(pwl + ch * 16);
    }
    __syncthreads();

    const int wid = tid >> 5;
    const int wr  = wid >> 2;     // warp row (0..1): M offset wr*64
    const int wc  = wid & 3;      // warp col (0..3): N offset wc*32

    wmma::fragment<wmma::accumulator, 16, 16, 16, float> acc[4][2];
#pragma unroll
    for (int i = 0; i < 4; i++)
#pragma unroll
        for (int j = 0; j < 2; j++) wmma::fill_fragment(acc[i][j], 0.0f);

#pragma unroll
    for (int kc = 0; kc < 8; kc++) {
        int k0 = kc * 16;
        wmma::fragment<wmma::matrix_a, 16, 16, 16, __nv_bfloat16, wmma::row_major> fah[4], fal[4];
        wmma::fragment<wmma::matrix_b, 16, 16, 16, __nv_bfloat16, wmma::col_major> fwh[2], fwl[2];
#pragma unroll
        for (int i = 0; i < 4; i++) {
            int m0 = wr * 64 + i * 16;
            wmma::load_matrix_sync(fah[i], Ahi + (size_t)m0 * LDM + k0, LDM);
            wmma::load_matrix_sync(fal[i], Alo + (size_t)m0 * LDM + k0, LDM);
        }
#pragma unroll
        for (int j = 0; j < 2; j++) {
            int n0 = wc * 32 + j * 16;
            wmma::load_matrix_sync(fwh[j], Whi + (size_t)n0 * LDM + k0, LDM);
            wmma::load_matrix_sync(fwl[j], Wlo + (size_t)n0 * LDM + k0, LDM);
        }
#pragma unroll
        for (int i = 0; i < 4; i++)
#pragma unroll
            for (int j = 0; j < 2; j++) {
                wmma::mma_sync(acc[i][j], fah[i], fwh[j], acc[i][j]);
                wmma::mma_sync(acc[i][j], fah[i], fwl[j], acc[i][j]);
                wmma::mma_sync(acc[i][j], fal[i], fwh[j], acc[i][j]);
            }
    }

    // store straight to gmem (bias folded into the scan kernel)
#pragma unroll
    for (int i = 0; i < 4; i++) {
        int m = bm + wr * 64 + i * 16;
#pragma unroll
        for (int j = 0; j < 2; j++) {
            int n = bn + wc * 32 + j * 16;
            wmma::store_matrix_sync(Cout + (size_t)m * G_ + n, acc[i][j], G_,
                                    wmma::mem_row_major);
        }
    }
}

// ---------------- sequential GRU scan: one CTA per batch element -----------
// gi: [T, B, 384] WITHOUT b_ih (added here); whh: [384,128]; bhh: [384]
// mode 0: write h as bf16 hi/lo at (t*B+b)*H+g
// mode 1: write h as f32 at (b*T+t)*H+g
__global__ __launch_bounds__(384, 1) void gru_scan(
    const float* __restrict__ gi,
    const float* __restrict__ whh,
    const float* __restrict__ bih,
    const float* __restrict__ bhh,
    float*         __restrict__ out_f32,
    __nv_bfloat16* __restrict__ out_hi,
    __nv_bfloat16* __restrict__ out_lo,
    int mode)
{
    __shared__ __align__(16) float h_sh[H_];
    __shared__ float gh_sh[G_];

    const int b = blockIdx.x;
    const int g = threadIdx.x;       // 0..383: gate row owned by this thread

    unsigned long long w2[64];
    {
        const float4* wrow = (const float4*)(whh + (size_t)g * H_);
#pragma unroll
        for (int i = 0; i < 32; i++) {
            float4 v = wrow[i];
            w2[2 * i + 0] = pk2(v.x, v.y);
            w2[2 * i + 1] = pk2(v.z, v.w);
        }
    }
    const float bias = bhh[g];

    float bir = 0.f, biz = 0.f, bin = 0.f;
    if (g < H_) {
        bir = bih[g];
        biz = bih[g + H_];
        bin = bih[g + 2 * H_];
        h_sh[g] = 0.0f;
    }

    float gi_r = 0.f, gi_z = 0.f, gi_n = 0.f;
    if (g < H_) {
        const float* p = gi + (size_t)b * G_;
        gi_r = p[g] + bir;
        gi_z = p[g + H_] + biz;
        gi_n = p[g + 2 * H_] + bin;
    }
    __syncthreads();

    for (int t = 0; t < T_; t++) {
        float nr = 0.f, nz = 0.f, nn = 0.f;
        if (g < H_ && t + 1 < T_) {
            const float* p = gi + ((size_t)(t + 1) * B_ + b) * G_;
            nr = p[g] + bir;
            nz = p[g + H_] + biz;
            nn = p[g + 2 * H_] + bin;
        }

        unsigned long long acc0 = pk2(bias, 0.0f);
        unsigned long long acc1 = pk2(0.0f, 0.0f);
        const ulonglong2* hq = (const ulonglong2*)h_sh;
#pragma unroll
        for (int i = 0; i < 32; i++) {
            ulonglong2 hv = hq[i];
            acc0 = fma2(w2[2 * i + 0], hv.x, acc0);
            acc1 = fma2(w2[2 * i + 1], hv.y, acc1);
        }
        float a0, a1, a2, a3;
        upk2(acc0, a0, a1);
        upk2(acc1, a2, a3);
        gh_sh[g] = (a0 + a2) + (a1 + a3);
        __syncthreads();

        if (g < H_) {
            float r  = sigm(gi_r + gh_sh[g]);
            float z  = sigm(gi_z + gh_sh[g + H_]);
            float n  = tanh_fast(gi_n + r * gh_sh[g + 2 * H_]);
            float hn = (1.0f - z) * n + z * h_sh[g];
            h_sh[g] = hn;
            if (mode == 0) {
                size_t o = ((size_t)t * B_ + b) * H_ + g;
                __nv_bfloat16 hh = __float2bfloat16(hn);
                out_hi[o] = hh;
                out_lo[o] = __float2bfloat16(hn - __bfloat162float(hh));
            } else {
                out_f32[((size_t)b * T_ + t) * H_ + g] = hn;
            }
            gi_r = nr; gi_z = nz; gi_n = nn;
        }
        __syncthreads();
    }
}

// ---------------- FC: out[M,32] = relu(Y[M,128] @ fcw[32,128]^T + fcb) -----
__global__ __launch_bounds__(256) void fc_kernel(
    const float* __restrict__ Y,
    const float* __restrict__ fcw,
    const float* __restrict__ fcb,
    float*       __restrict__ out)
{
    __shared__ float Wt[128][33];
    __shared__ float As[128][33];

    const int bm  = blockIdx.x * 32;
    const int tid = threadIdx.x;

#pragma unroll
    for (int j = 0; j < 4; j++) {
        int f  = tid + j * 256;
        int c  = f >> 5;
        int kq = f & 31;
        float4 v = *(const float4*)(fcw + (size_t)c * 128 + kq * 4);
        Wt[kq * 4 + 0][c] = v.x;
        Wt[kq * 4 + 1][c] = v.y;
        Wt[kq * 4 + 2][c] = v.z;
        Wt[kq * 4 + 3][c] = v.w;
    }
#pragma unroll
    for (int j = 0; j < 4; j++) {
        int f  = tid + j * 256;
        int r  = f >> 5;
        int kq = f & 31;
        float4 v = *(const float4*)(Y + (size_t)(bm + r) * 128 + kq * 4);
        As[kq * 4 + 0][r] = v.x;
        As[kq * 4 + 1][r] = v.y;
        As[kq * 4 + 2][r] = v.z;
        As[kq * 4 + 3][r] = v.w;
    }
    __syncthreads();

    const int c  = tid & 31;
    const int rg = tid >> 5;
    float acc[4] = {0.f, 0.f, 0.f, 0.f};
#pragma unroll
    for (int k = 0; k < 128; k++) {
        float w = Wt[k][c];
#pragma unroll
        for (int i = 0; i < 4; i++) acc[i] += As[k][rg * 4 + i] * w;
    }
    float bb = fcb[c];
#pragma unroll
    for (int i = 0; i < 4; i++) {
        float v = acc[i] + bb;
        out[(size_t)(bm + rg * 4 + i) * C_ + c] = fmaxf(v, 0.0f);
    }
}

// ---------------- launch ----------------------------------------------------
extern "C" void kernel_launch(void* const* d_in, const int* in_sizes, int n_in,
                              void* d_out, int out_size)
{
    const int*   x    = (const int*)  d_in[0];
    const float* emb  = (const float*)d_in[1];
    const float* wih0 = (const float*)d_in[2];
    const float* whh0 = (const float*)d_in[3];
    const float* bih0 = (const float*)d_in[4];
    const float* bhh0 = (const float*)d_in[5];
    const float* wih1 = (const float*)d_in[6];
    const float* whh1 = (const float*)d_in[7];
    const float* bih1 = (const float*)d_in[8];
    const float* bhh1 = (const float*)d_in[9];
    const float* fcw  = (const float*)d_in[10];
    const float* fcb  = (const float*)d_in[11];
    float* out = (float*)d_out;

    void* p;
    cudaGetSymbolAddress(&p, g_gi);      float* gi   = (float*)p;
    cudaGetSymbolAddress(&p, g_y);       float* y    = (float*)p;
    cudaGetSymbolAddress(&p, g_hseq_hi); __nv_bfloat16* hhi = (__nv_bfloat16*)p;
    cudaGetSymbolAddress(&p, g_hseq_lo); __nv_bfloat16* hlo = (__nv_bfloat16*)p;
    cudaGetSymbolAddress(&p, g_emb_hi);  __nv_bfloat16* ehi = (__nv_bfloat16*)p;
    cudaGetSymbolAddress(&p, g_emb_lo);  __nv_bfloat16* elo = (__nv_bfloat16*)p;
    cudaGetSymbolAddress(&p, g_w0_hi);   __nv_bfloat16* w0h = (__nv_bfloat16*)p;
    cudaGetSymbolAddress(&p, g_w0_lo);   __nv_bfloat16* w0l = (__nv_bfloat16*)p;
    cudaGetSymbolAddress(&p, g_w1_hi);   __nv_bfloat16* w1h = (__nv_bfloat16*)p;
    cudaGetSymbolAddress(&p, g_w1_lo);   __nv_bfloat16* w1l = (__nv_bfloat16*)p;

    cudaFuncSetAttribute(gemm_wmma, cudaFuncAttributeMaxDynamicSharedMemorySize, SM_TOT);

    // 0) split emb + input-gate weights into bf16 hi/lo
    long nconv = (long)V_ * H_ + 2L * G_ * H_;
    convert_kernel<<<(unsigned)((nconv + 255) / 256), 256>>>(emb, wih0, wih1);

    dim3 ggrid(G_ / 128, M_ / 128);   // (3, 1024)

    // 1) gi0 = gather(emb, x) @ w_ih0^T                [T,B,384]
    gemm_wmma<<<ggrid, 256, SM_TOT>>>(x, ehi, elo, w0h, w0l, gi, 1);

    // 2) layer-0 scan (adds b_ih0) -> hseq as bf16 hi/lo [T,B,128]
    gru_scan<<<B_, 384>>>(gi, whh0, bih0, bhh0, nullptr, hhi, hlo, 0);

    // 3) gi1 = hseq @ w_ih1^T                          [T,B,384]
    gemm_wmma<<<ggrid, 256, SM_TOT>>>(nullptr, hhi, hlo, w1h, w1l, gi, 0);

    // 4) layer-1 scan (adds b_ih1) -> y f32 [B,T,128]
    gru_scan<<<B_, 384>>>(gi, whh1, bih1, bhh1, y, nullptr, nullptr, 1);

    // 5) out = relu(y @ fc_w^T + fc_b)                 [B*T, 32]
    fc_kernel<<<M_ / 32, 256>>>(y, fcw, fcb, out);
}

// round 6
// speedup vs baseline: 1.3934x; 1.3351x over previous
#include <cuda_runtime.h>
#include <cuda_bf16.h>
#include <mma.h>
#include <cstdint>

using namespace nvcuda;

// Problem constants (fixed by the dataset)
#define T_ 2048
#define B_ 64
#define H_ 128
#define G_ 384          // 3*H
#define C_ 32
#define M_ (T_ * B_)    // 131072 rows
#define V_ 50257

// ---------------- scratch (device globals; no allocation allowed) ----------
__device__ float g_gi[(size_t)M_ * G_];            // input gates, [T, B, 384] (no b_ih)
__device__ float g_y[(size_t)M_ * H_];             // layer-1 output, [B, T, 128]
__device__ __nv_bfloat16 g_hseq_hi[(size_t)M_ * H_];   // layer-0 out hi, [T,B,128]
__device__ __nv_bfloat16 g_hseq_lo[(size_t)M_ * H_];   // layer-0 out lo
__device__ __nv_bfloat16 g_emb_hi[(size_t)V_ * H_];
__device__ __nv_bfloat16 g_emb_lo[(size_t)V_ * H_];
__device__ __nv_bfloat16 g_w0_hi[G_ * H_];
__device__ __nv_bfloat16 g_w0_lo[G_ * H_];
__device__ __nv_bfloat16 g_w1_hi[G_ * H_];
__device__ __nv_bfloat16 g_w1_lo[G_ * H_];

// ---------------- helpers ---------------------------------------------------
static __device__ __forceinline__ unsigned long long pk2(float a, float b) {
    unsigned long long r;
    asm("mov.b64 %0, {%1,%2};" : "=l"(r) : "f"(a), "f"(b));
    return r;
}
static __device__ __forceinline__ void upk2(unsigned long long v, float& a, float& b) {
    asm("mov.b64 {%0,%1}, %2;" : "=f"(a), "=f"(b) : "l"(v));
}
// packed fp32x2 FMA (Blackwell)
static __device__ __forceinline__ unsigned long long fma2(
    unsigned long long a, unsigned long long b, unsigned long long c) {
    unsigned long long d;
    asm("fma.rn.f32x2 %0, %1, %2, %3;" : "=l"(d) : "l"(a), "l"(b), "l"(c));
    return d;
}
static __device__ __forceinline__ float sigm(float x) {
    return __fdividef(1.0f, 1.0f + __expf(-x));
}
static __device__ __forceinline__ float tanh_fast(float x) {
    x = fminf(15.0f, fmaxf(-15.0f, x));
    float e = __expf(2.0f * x);
    return __fdividef(e - 1.0f, e + 1.0f);
}

// ---------------- fp32 -> bf16 hi/lo split conversion ----------------------
__global__ __launch_bounds__(256) void convert_kernel(
    const float* __restrict__ emb, const float* __restrict__ w0,
    const float* __restrict__ w1)
{
    long i = (long)blockIdx.x * 256 + threadIdx.x;
    const long NE = (long)V_ * H_;
    const long NW = (long)G_ * H_;
    if (i < NE) {
        float v = emb[i];
        __nv_bfloat16 h = __float2bfloat16(v);
        g_emb_hi[i] = h;
        g_emb_lo[i] = __float2bfloat16(v - __bfloat162float(h));
        return;
    }
    long j = i - NE;
    if (j < NW) {
        float v = w0[j];
        __nv_bfloat16 h = __float2bfloat16(v);
        g_w0_hi[j] = h;
        g_w0_lo[j] = __float2bfloat16(v - __bfloat162float(h));
        return;
    }
    j -= NW;
    if (j < NW) {
        float v = w1[j];
        __nv_bfloat16 h = __float2bfloat16(v);
        g_w1_hi[j] = h;
        g_w1_lo[j] = __float2bfloat16(v - __bfloat162float(h));
    }
}

// ---------------- WMMA GEMM: C[M,384] = A[M,128] @ W[384,128]^T ------------
#define LDM 136                      // padded leading dim (bf16 elems)
#define TILE_B (128 * LDM * 2)       // bytes per bf16 tile (34816)
#define SM_TOT (4 * TILE_B)          // Ahi, Alo, Whi, Wlo

__global__ __launch_bounds__(256, 1) void gemm_wmma(
    const int*           __restrict__ x,      // tokens [B,T] (gather mode)
    const __nv_bfloat16* __restrict__ a_hi,
    const __nv_bfloat16* __restrict__ a_lo,
    const __nv_bfloat16* __restrict__ w_hi,
    const __nv_bfloat16* __restrict__ w_lo,
    float*               __restrict__ Cout,
    int gather)
{
    extern __shared__ __align__(16) char smem[];
    __nv_bfloat16* Ahi = (__nv_bfloat16*)(smem);
    __nv_bfloat16* Alo = (__nv_bfloat16*)(smem + TILE_B);
    __nv_bfloat16* Whi = (__nv_bfloat16*)(smem + 2 * TILE_B);
    __nv_bfloat16* Wlo = (__nv_bfloat16*)(smem + 3 * TILE_B);

    const int tid = threadIdx.x;
    const int bn  = blockIdx.x * 128;
    const int bm  = blockIdx.y * 128;

#pragma unroll
    for (int it = 0; it < 8; it++) {
        int i   = tid + it * 256;           // 0..2047
        int row = i >> 4;
        int ch  = (i & 15);                 // 16B chunk index in row
        const char *pah, *pal;
        if (gather) {
            int m = bm + row;
            int token = x[(m & (B_ - 1)) * T_ + (m >> 6)];
            pah = (const char*)(a_hi + (size_t)token * H_);
            pal = (const char*)(a_lo + (size_t)token * H_);
        } else {
            pah = (const char*)(a_hi + (size_t)(bm + row) * H_);
            pal = (const char*)(a_lo + (size_t)(bm + row) * H_);
        }
        const char* pwh = (const char*)(w_hi + (size_t)(bn + row) * H_);
        const char* pwl = (const char*)(w_lo + (size_t)(bn + row) * H_);
        size_t doff = (size_t)row * LDM + ch * 8;   // elem offset in smem tile
        *(uint4*)(Ahi + doff) = *(const uint4*)(pah + ch * 16);
        *(uint4*)(Alo + doff) = *(const uint4*)(pal + ch * 16);
        *(uint4*)(Whi + doff) = *(const uint4*)(pwh + ch * 16);
        *(uint4*)(Wlo + doff) = *(const uint4*)(pwl + ch * 16);
    }
    __syncthreads();

    const int wid = tid >> 5;
    const int wr  = wid >> 2;     // warp row (0..1): M offset wr*64
    const int wc  = wid & 3;      // warp col (0..3): N offset wc*32

    wmma::fragment<wmma::accumulator, 16, 16, 16, float> acc[4][2];
#pragma unroll
    for (int i = 0; i < 4; i++)
#pragma unroll
        for (int j = 0; j < 2; j++) wmma::fill_fragment(acc[i][j], 0.0f);

#pragma unroll
    for (int kc = 0; kc < 8; kc++) {
        int k0 = kc * 16;
        wmma::fragment<wmma::matrix_a, 16, 16, 16, __nv_bfloat16, wmma::row_major> fah[4], fal[4];
        wmma::fragment<wmma::matrix_b, 16, 16, 16, __nv_bfloat16, wmma::col_major> fwh[2], fwl[2];
#pragma unroll
        for (int i = 0; i < 4; i++) {
            int m0 = wr * 64 + i * 16;
            wmma::load_matrix_sync(fah[i], Ahi + (size_t)m0 * LDM + k0, LDM);
            wmma::load_matrix_sync(fal[i], Alo + (size_t)m0 * LDM + k0, LDM);
        }
#pragma unroll
        for (int j = 0; j < 2; j++) {
            int n0 = wc * 32 + j * 16;
            wmma::load_matrix_sync(fwh[j], Whi + (size_t)n0 * LDM + k0, LDM);
            wmma::load_matrix_sync(fwl[j], Wlo + (size_t)n0 * LDM + k0, LDM);
        }
#pragma unroll
        for (int i = 0; i < 4; i++)
#pragma unroll
            for (int j = 0; j < 2; j++) {
                wmma::mma_sync(acc[i][j], fah[i], fwh[j], acc[i][j]);
                wmma::mma_sync(acc[i][j], fah[i], fwl[j], acc[i][j]);
                wmma::mma_sync(acc[i][j], fal[i], fwh[j], acc[i][j]);
            }
    }

#pragma unroll
    for (int i = 0; i < 4; i++) {
        int m = bm + wr * 64 + i * 16;
#pragma unroll
        for (int j = 0; j < 2; j++) {
            int n = bn + wc * 32 + j * 16;
            wmma::store_matrix_sync(Cout + (size_t)m * G_ + n, acc[i][j], G_,
                                    wmma::mem_row_major);
        }
    }
}

// ---------------- sequential GRU scan: one CTA per batch element -----------
// gi: [T, B, 384] WITHOUT b_ih (added here); whh: [384,128]; bhh/bih: [384]
// Group-specialized gates: grp0 (rows 0..127)  computes r before bar A,
//                          grp1 (rows 128..255) computes z before bar A,
//                          grp2 (rows 256..383) computes n + h after bar A.
// mode 0: write h as bf16 hi/lo at (t*B+b)*H+j ; mode 1: f32 at (b*T+t)*H+j
__global__ __launch_bounds__(384, 1) void gru_scan(
    const float* __restrict__ gi,
    const float* __restrict__ whh,
    const float* __restrict__ bih,
    const float* __restrict__ bhh,
    float*         __restrict__ out_f32,
    __nv_bfloat16* __restrict__ out_hi,
    __nv_bfloat16* __restrict__ out_lo,
    int mode)
{
    __shared__ __align__(16) float h_sh[H_];
    __shared__ float r_sh[H_];
    __shared__ float z_sh[H_];

    const int b   = blockIdx.x;
    const int g   = threadIdx.x;     // 0..383: gate row owned by this thread
    const int grp = g >> 7;          // 0=r, 1=z, 2=n
    const int j   = g & 127;

    // This thread's 128 W_hh weights as 64 f32x2 pairs (128 regs).
    unsigned long long w2[64];
    {
        const float4* wrow = (const float4*)(whh + (size_t)g * H_);
#pragma unroll
        for (int i = 0; i < 32; i++) {
            float4 v = wrow[i];
            w2[2 * i + 0] = pk2(v.x, v.y);
            w2[2 * i + 1] = pk2(v.z, v.w);
        }
    }
    const float bh = bhh[g];
    const float bi = bih[g];

    if (g < H_) h_sh[g] = 0.0f;

    // each thread prefetches ONLY its own gate input (+ b_ih)
    float gic = gi[(size_t)b * G_ + g] + bi;
    __syncthreads();

    const unsigned long long z64 = pk2(0.0f, 0.0f);

    for (int t = 0; t < T_; t++) {
        float ginext = 0.0f;
        if (t + 1 < T_)
            ginext = gi[((size_t)(t + 1) * B_ + b) * G_ + g] + bi;

        // gh = bh + W_hh[g,:] . h   -- 4 independent fma2 chains
        unsigned long long acc0 = pk2(bh, 0.0f);
        unsigned long long acc1 = z64, acc2 = z64, acc3 = z64;
        const ulonglong2* hq = (const ulonglong2*)h_sh;
#pragma unroll
        for (int i = 0; i < 16; i++) {
            ulonglong2 hv0 = hq[2 * i + 0];
            ulonglong2 hv1 = hq[2 * i + 1];
            acc0 = fma2(w2[4 * i + 0], hv0.x, acc0);
            acc1 = fma2(w2[4 * i + 1], hv0.y, acc1);
            acc2 = fma2(w2[4 * i + 2], hv1.x, acc2);
            acc3 = fma2(w2[4 * i + 3], hv1.y, acc3);
        }
        float a0, a1, a2, a3, a4, a5, a6, a7;
        upk2(acc0, a0, a1); upk2(acc1, a2, a3);
        upk2(acc2, a4, a5); upk2(acc3, a6, a7);
        float ghval = ((a0 + a2) + (a1 + a3)) + ((a4 + a6) + (a5 + a7));

        // r and z computed by their owner groups BEFORE the barrier
        if (grp == 0) r_sh[j] = sigm(gic + ghval);
        else if (grp == 1) z_sh[j] = sigm(gic + ghval);
        __syncthreads();   // bar A: r_sh/z_sh visible; all h_sh reads done

        if (grp == 2) {
            float n  = tanh_fast(gic + r_sh[j] * ghval);
            float z  = z_sh[j];
            float hn = (1.0f - z) * n + z * h_sh[j];
            h_sh[j] = hn;
            if (mode == 0) {
                size_t o = ((size_t)t * B_ + b) * H_ + j;
                __nv_bfloat16 hh = __float2bfloat16(hn);
                out_hi[o] = hh;
                out_lo[o] = __float2bfloat16(hn - __bfloat162float(hh));
            } else {
                out_f32[((size_t)b * T_ + t) * H_ + j] = hn;
            }
        }
        gic = ginext;
        __syncthreads();   // bar B: new h visible before next dot
    }
}

// ---------------- FC: out[M,32] = relu(Y[M,128] @ fcw[32,128]^T + fcb) -----
__global__ __launch_bounds__(256) void fc_kernel(
    const float* __restrict__ Y,
    const float* __restrict__ fcw,
    const float* __restrict__ fcb,
    float*       __restrict__ out)
{
    __shared__ float Wt[128][33];
    __shared__ float As[128][33];

    const int bm  = blockIdx.x * 32;
    const int tid = threadIdx.x;

#pragma unroll
    for (int j = 0; j < 4; j++) {
        int f  = tid + j * 256;
        int c  = f >> 5;
        int kq = f & 31;
        float4 v = *(const float4*)(fcw + (size_t)c * 128 + kq * 4);
        Wt[kq * 4 + 0][c] = v.x;
        Wt[kq * 4 + 1][c] = v.y;
        Wt[kq * 4 + 2][c] = v.z;
        Wt[kq * 4 + 3][c] = v.w;
    }
#pragma unroll
    for (int j = 0; j < 4; j++) {
        int f  = tid + j * 256;
        int r  = f >> 5;
        int kq = f & 31;
        float4 v = *(const float4*)(Y + (size_t)(bm + r) * 128 + kq * 4);
        As[kq * 4 + 0][r] = v.x;
        As[kq * 4 + 1][r] = v.y;
        As[kq * 4 + 2][r] = v.z;
        As[kq * 4 + 3][r] = v.w;
    }
    __syncthreads();

    const int c  = tid & 31;
    const int rg = tid >> 5;
    float acc[4] = {0.f, 0.f, 0.f, 0.f};
#pragma unroll
    for (int k = 0; k < 128; k++) {
        float w = Wt[k][c];
#pragma unroll
        for (int i = 0; i < 4; i++) acc[i] += As[k][rg * 4 + i] * w;
    }
    float bb = fcb[c];
#pragma unroll
    for (int i = 0; i < 4; i++) {
        float v = acc[i] + bb;
        out[(size_t)(bm + rg * 4 + i) * C_ + c] = fmaxf(v, 0.0f);
    }
}

// ---------------- launch ----------------------------------------------------
extern "C" void kernel_launch(void* const* d_in, const int* in_sizes, int n_in,
                              void* d_out, int out_size)
{
    const int*   x    = (const int*)  d_in[0];
    const float* emb  = (const float*)d_in[1];
    const float* wih0 = (const float*)d_in[2];
    const float* whh0 = (const float*)d_in[3];
    const float* bih0 = (const float*)d_in[4];
    const float* bhh0 = (const float*)d_in[5];
    const float* wih1 = (const float*)d_in[6];
    const float* whh1 = (const float*)d_in[7];
    const float* bih1 = (const float*)d_in[8];
    const float* bhh1 = (const float*)d_in[9];
    const float* fcw  = (const float*)d_in[10];
    const float* fcb  = (const float*)d_in[11];
    float* out = (float*)d_out;

    void* p;
    cudaGetSymbolAddress(&p, g_gi);      float* gi   = (float*)p;
    cudaGetSymbolAddress(&p, g_y);       float* y    = (float*)p;
    cudaGetSymbolAddress(&p, g_hseq_hi); __nv_bfloat16* hhi = (__nv_bfloat16*)p;
    cudaGetSymbolAddress(&p, g_hseq_lo); __nv_bfloat16* hlo = (__nv_bfloat16*)p;
    cudaGetSymbolAddress(&p, g_emb_hi);  __nv_bfloat16* ehi = (__nv_bfloat16*)p;
    cudaGetSymbolAddress(&p, g_emb_lo);  __nv_bfloat16* elo = (__nv_bfloat16*)p;
    cudaGetSymbolAddress(&p, g_w0_hi);   __nv_bfloat16* w0h = (__nv_bfloat16*)p;
    cudaGetSymbolAddress(&p, g_w0_lo);   __nv_bfloat16* w0l = (__nv_bfloat16*)p;
    cudaGetSymbolAddress(&p, g_w1_hi);   __nv_bfloat16* w1h = (__nv_bfloat16*)p;
    cudaGetSymbolAddress(&p, g_w1_lo);   __nv_bfloat16* w1l = (__nv_bfloat16*)p;

    cudaFuncSetAttribute(gemm_wmma, cudaFuncAttributeMaxDynamicSharedMemorySize, SM_TOT);

    // 0) split emb + input-gate weights into bf16 hi/lo
    long nconv = (long)V_ * H_ + 2L * G_ * H_;
    convert_kernel<<<(unsigned)((nconv + 255) / 256), 256>>>(emb, wih0, wih1);

    dim3 ggrid(G_ / 128, M_ / 128);   // (3, 1024)

    // 1) gi0 = gather(emb, x) @ w_ih0^T                [T,B,384]
    gemm_wmma<<<ggrid, 256, SM_TOT>>>(x, ehi, elo, w0h, w0l, gi, 1);

    // 2) layer-0 scan (adds b_ih0) -> hseq as bf16 hi/lo [T,B,128]
    gru_scan<<<B_, 384>>>(gi, whh0, bih0, bhh0, nullptr, hhi, hlo, 0);

    // 3) gi1 = hseq @ w_ih1^T                          [T,B,384]
    gemm_wmma<<<ggrid, 256, SM_TOT>>>(nullptr, hhi, hlo, w1h, w1l, gi, 0);

    // 4) layer-1 scan (adds b_ih1) -> y f32 [B,T,128]
    gru_scan<<<B_, 384>>>(gi, whh1, bih1, bhh1, y, nullptr, nullptr, 1);

    // 5) out = relu(y @ fc_w^T + fc_b)                 [B*T, 32]
    fc_kernel<<<M_ / 32, 256>>>(y, fcw, fcb, out);
}

// round 8
// speedup vs baseline: 2.0864x; 1.4973x over previous
#include <cuda_runtime.h>
#include <cuda_bf16.h>
#include <mma.h>
#include <cstdint>

using namespace nvcuda;

// Problem constants (fixed by the dataset)
#define T_ 2048
#define B_ 64
#define H_ 128
#define G_ 384          // 3*H
#define C_ 32
#define M_ (T_ * B_)    // 131072 rows
#define V_ 50257

// ---------------- scratch (device globals; no allocation allowed) ----------
__device__ float g_gi0[(size_t)M_ * G_];           // layer-0 input gates [T,B,384]
__device__ float g_gi1[(size_t)M_ * G_];           // layer-1 input gates [T,B,384]
__device__ float g_y[(size_t)M_ * H_];             // layer-1 output, [B, T, 128]
__device__ __nv_bfloat16 g_hseq_hi[(size_t)M_ * H_];   // layer-0 out hi, [T,B,128]
__device__ __nv_bfloat16 g_hseq_lo[(size_t)M_ * H_];   // layer-0 out lo
__device__ __nv_bfloat16 g_emb_hi[(size_t)V_ * H_];
__device__ __nv_bfloat16 g_emb_lo[(size_t)V_ * H_];
__device__ __nv_bfloat16 g_w0_hi[G_ * H_];
__device__ __nv_bfloat16 g_w0_lo[G_ * H_];
__device__ __nv_bfloat16 g_w1_hi[G_ * H_];
__device__ __nv_bfloat16 g_w1_lo[G_ * H_];

// pipeline flags
#define NCHUNK 64                    // 64 chunks of 32 timesteps
#define TILES_M 1024                 // M_/128
#define TILES_N 4                    // G_/96
#define NTILES (TILES_M * TILES_N)   // 4096
#define TILES_PER_CHUNK 64           // 16 m-tiles * 4 n-tiles
__device__ int g_cnt0[NCHUNK];       // L0 chunks done (counts to 64 CTAs)
__device__ int g_gcnt1[NCHUNK];      // gi1 tiles done per chunk (counts to 64)
__device__ int g_ticket;             // worker tile ticket

// ---------------- helpers ---------------------------------------------------
static __device__ __forceinline__ unsigned long long pk2(float a, float b) {
    unsigned long long r;
    asm("mov.b64 %0, {%1,%2};" : "=l"(r) : "f"(a), "f"(b));
    return r;
}
static __device__ __forceinline__ void upk2(unsigned long long v, float& a, float& b) {
    asm("mov.b64 {%0,%1}, %2;" : "=f"(a), "=f"(b) : "l"(v));
}
static __device__ __forceinline__ unsigned long long fma2(
    unsigned long long a, unsigned long long b, unsigned long long c) {
    unsigned long long d;
    asm("fma.rn.f32x2 %0, %1, %2, %3;" : "=l"(d) : "l"(a), "l"(b), "l"(c));
    return d;
}
static __device__ __forceinline__ float sigm(float x) {
    return __fdividef(1.0f, 1.0f + __expf(-x));
}
static __device__ __forceinline__ float tanh_fast(float x) {
    x = fminf(15.0f, fmaxf(-15.0f, x));
    float e = __expf(2.0f * x);
    return __fdividef(e - 1.0f, e + 1.0f);
}

// ---------------- fp32 -> bf16 hi/lo split conversion ----------------------
__global__ __launch_bounds__(256) void convert_kernel(
    const float* __restrict__ emb, const float* __restrict__ w0,
    const float* __restrict__ w1)
{
    long i = (long)blockIdx.x * 256 + threadIdx.x;
    const long NE = (long)V_ * H_;
    const long NW = (long)G_ * H_;
    if (i < NE) {
        float v = emb[i];
        __nv_bfloat16 h = __float2bfloat16(v);
        g_emb_hi[i] = h;
        g_emb_lo[i] = __float2bfloat16(v - __bfloat162float(h));
        return;
    }
    long j = i - NE;
    if (j < NW) {
        float v = w0[j];
        __nv_bfloat16 h = __float2bfloat16(v);
        g_w0_hi[j] = h;
        g_w0_lo[j] = __float2bfloat16(v - __bfloat162float(h));
        return;
    }
    j -= NW;
    if (j < NW) {
        float v = w1[j];
        __nv_bfloat16 h = __float2bfloat16(v);
        g_w1_hi[j] = h;
        g_w1_lo[j] = __float2bfloat16(v - __bfloat162float(h));
    }
}

// ---------------- flag reset (every replay, before fused kernel) -----------
__global__ void zero_flags() {
    int i = threadIdx.x;
    if (i < NCHUNK) { g_cnt0[i] = 0; g_gcnt1[i] = 0; }
    if (i == 0) g_ticket = 0;
}

// ---------------- full-chip WMMA GEMM for gi0 (gather path) ----------------
#define LDM 136                      // padded leading dim (bf16 elems)
#define TILE_B (128 * LDM * 2)       // bytes per bf16 tile (34816)
#define SM_TOT (4 * TILE_B)

__global__ __launch_bounds__(256, 1) void gemm_wmma(
    const int*           __restrict__ x,
    const __nv_bfloat16* __restrict__ a_hi,
    const __nv_bfloat16* __restrict__ a_lo,
    const __nv_bfloat16* __restrict__ w_hi,
    const __nv_bfloat16* __restrict__ w_lo,
    float*               __restrict__ Cout)
{
    extern __shared__ __align__(16) char smem[];
    __nv_bfloat16* Ahi = (__nv_bfloat16*)(smem);
    __nv_bfloat16* Alo = (__nv_bfloat16*)(smem + TILE_B);
    __nv_bfloat16* Whi = (__nv_bfloat16*)(smem + 2 * TILE_B);
    __nv_bfloat16* Wlo = (__nv_bfloat16*)(smem + 3 * TILE_B);

    const int tid = threadIdx.x;
    const int bn  = blockIdx.x * 128;
    const int bm  = blockIdx.y * 128;

#pragma unroll
    for (int it = 0; it < 8; it++) {
        int i   = tid + it * 256;
        int row = i >> 4;
        int ch  = (i & 15);
        int m = bm + row;
        int token = x[(m & (B_ - 1)) * T_ + (m >> 6)];
        const char* pah = (const char*)(a_hi + (size_t)token * H_);
        const char* pal = (const char*)(a_lo + (size_t)token * H_);
        const char* pwh = (const char*)(w_hi + (size_t)(bn + row) * H_);
        const char* pwl = (const char*)(w_lo + (size_t)(bn + row) * H_);
        size_t doff = (size_t)row * LDM + ch * 8;
        *(uint4*)(Ahi + doff) = *(const uint4*)(pah + ch * 16);
        *(uint4*)(Alo + doff) = *(const uint4*)(pal + ch * 16);
        *(uint4*)(Whi + doff) = *(const uint4*)(pwh + ch * 16);
        *(uint4*)(Wlo + doff) = *(const uint4*)(pwl + ch * 16);
    }
    __syncthreads();

    const int wid = tid >> 5;
    const int wr  = wid >> 2;
    const int wc  = wid & 3;

    wmma::fragment<wmma::accumulator, 16, 16, 16, float> acc[4][2];
#pragma unroll
    for (int i = 0; i < 4; i++)
#pragma unroll
        for (int j = 0; j < 2; j++) wmma::fill_fragment(acc[i][j], 0.0f);

#pragma unroll
    for (int kc = 0; kc < 8; kc++) {
        int k0 = kc * 16;
        wmma::fragment<wmma::matrix_a, 16, 16, 16, __nv_bfloat16, wmma::row_major> fah[4], fal[4];
        wmma::fragment<wmma::matrix_b, 16, 16, 16, __nv_bfloat16, wmma::col_major> fwh[2], fwl[2];
#pragma unroll
        for (int i = 0; i < 4; i++) {
            int m0 = wr * 64 + i * 16;
            wmma::load_matrix_sync(fah[i], Ahi + (size_t)m0 * LDM + k0, LDM);
            wmma::load_matrix_sync(fal[i], Alo + (size_t)m0 * LDM + k0, LDM);
        }
#pragma unroll
        for (int j = 0; j < 2; j++) {
            int n0 = wc * 32 + j * 16;
            wmma::load_matrix_sync(fwh[j], Whi + (size_t)n0 * LDM + k0, LDM);
            wmma::load_matrix_sync(fwl[j], Wlo + (size_t)n0 * LDM + k0, LDM);
        }
#pragma unroll
        for (int i = 0; i < 4; i++)
#pragma unroll
            for (int j = 0; j < 2; j++) {
                wmma::mma_sync(acc[i][j], fah[i], fwh[j], acc[i][j]);
                wmma::mma_sync(acc[i][j], fah[i], fwl[j], acc[i][j]);
                wmma::mma_sync(acc[i][j], fal[i], fwh[j], acc[i][j]);
            }
    }

#pragma unroll
    for (int i = 0; i < 4; i++) {
        int m = bm + wr * 64 + i * 16;
#pragma unroll
        for (int j = 0; j < 2; j++) {
            int n = bn + wc * 32 + j * 16;
            wmma::store_matrix_sync(Cout + (size_t)m * G_ + n, acc[i][j], G_,
                                    wmma::mem_row_major);
        }
    }
}

// ---------------- fused pipeline kernel: L0 scan | GEMM1 workers | L1 scan --
// Worker smem: Ahi(128 rows) Alo Whi(96) Wlo, LDM=136 bf16 rows.
#define WSM_AHI 0
#define WSM_ALO 34816
#define WSM_WHI 69632
#define WSM_WLO 95744
#define WSM_TOT 121856

// ---- L0 scan body (publishes chunk flags) ----
static __device__ __forceinline__ void scan_l0(
    char* dsm, int b,
    const float* __restrict__ gi,
    const float* __restrict__ whh,
    const float* __restrict__ bih,
    const float* __restrict__ bhh,
    __nv_bfloat16* __restrict__ out_hi,
    __nv_bfloat16* __restrict__ out_lo)
{
    float* h_sh = (float*)dsm;          // [128]
    float* r_sh = h_sh + H_;
    float* z_sh = r_sh + H_;

    const int g   = threadIdx.x;
    const int grp = g >> 7;
    const int j   = g & 127;

    unsigned long long w2[64];
    {
        const float4* wrow = (const float4*)(whh + (size_t)g * H_);
#pragma unroll
        for (int i = 0; i < 32; i++) {
            float4 v = wrow[i];
            w2[2 * i + 0] = pk2(v.x, v.y);
            w2[2 * i + 1] = pk2(v.z, v.w);
        }
    }
    const float bh = bhh[g];
    const float bi = bih[g];

    if (g < H_) h_sh[g] = 0.0f;
    float gic = gi[(size_t)b * G_ + g] + bi;
    __syncthreads();

    const unsigned long long z64 = pk2(0.0f, 0.0f);

    for (int t = 0; t < T_; t++) {
        float ginext = 0.0f;
        if (t + 1 < T_)
            ginext = gi[((size_t)(t + 1) * B_ + b) * G_ + g] + bi;

        unsigned long long acc0 = pk2(bh, 0.0f);
        unsigned long long acc1 = z64, acc2 = z64, acc3 = z64;
        const ulonglong2* hq = (const ulonglong2*)h_sh;
#pragma unroll
        for (int i = 0; i < 16; i++) {
            ulonglong2 hv0 = hq[2 * i + 0];
            ulonglong2 hv1 = hq[2 * i + 1];
            acc0 = fma2(w2[4 * i + 0], hv0.x, acc0);
            acc1 = fma2(w2[4 * i + 1], hv0.y, acc1);
            acc2 = fma2(w2[4 * i + 2], hv1.x, acc2);
            acc3 = fma2(w2[4 * i + 3], hv1.y, acc3);
        }
        float a0, a1, a2, a3, a4, a5, a6, a7;
        upk2(acc0, a0, a1); upk2(acc1, a2, a3);
        upk2(acc2, a4, a5); upk2(acc3, a6, a7);
        float ghval = ((a0 + a2) + (a1 + a3)) + ((a4 + a6) + (a5 + a7));

        if (grp == 0) r_sh[j] = sigm(gic + ghval);
        else if (grp == 1) z_sh[j] = sigm(gic + ghval);
        __syncthreads();   // bar A

        if (grp == 2) {
            float n  = tanh_fast(gic + r_sh[j] * ghval);
            float z  = z_sh[j];
            float hn = (1.0f - z) * n + z * h_sh[j];
            h_sh[j] = hn;
            size_t o = ((size_t)t * B_ + b) * H_ + j;
            __nv_bfloat16 hh = __float2bfloat16(hn);
            out_hi[o] = hh;
            out_lo[o] = __float2bfloat16(hn - __bfloat162float(hh));
            if ((t & 31) == 31) __threadfence();   // release stores of this chunk
        }
        gic = ginext;
        __syncthreads();   // bar B
        if (((t & 31) == 31) && g == 0)
            atomicAdd(&g_cnt0[t >> 5], 1);
    }
}

// ---- L1 scan body (waits on gi1 chunk flags) ----
static __device__ __forceinline__ void scan_l1(
    char* dsm, int b,
    const float* __restrict__ gi,
    const float* __restrict__ whh,
    const float* __restrict__ bih,
    const float* __restrict__ bhh,
    float* __restrict__ out_f32)
{
    float* h_sh = (float*)dsm;
    float* r_sh = h_sh + H_;
    float* z_sh = r_sh + H_;

    const int g   = threadIdx.x;
    const int grp = g >> 7;
    const int j   = g & 127;

    unsigned long long w2[64];
    {
        const float4* wrow = (const float4*)(whh + (size_t)g * H_);
#pragma unroll
        for (int i = 0; i < 32; i++) {
            float4 v = wrow[i];
            w2[2 * i + 0] = pk2(v.x, v.y);
            w2[2 * i + 1] = pk2(v.z, v.w);
        }
    }
    const float bh = bhh[g];
    const float bi = bih[g];

    if (g < H_) h_sh[g] = 0.0f;
    __syncthreads();

    // wait for first gi1 chunk
    if (g == 0)
        while (*(volatile int*)&g_gcnt1[0] < TILES_PER_CHUNK) __nanosleep(128);
    __syncthreads();
    float gic = __ldcg(&gi[(size_t)b * G_ + g]) + bi;

    const unsigned long long z64 = pk2(0.0f, 0.0f);

    for (int t = 0; t < T_; t++) {
        bool newchunk = ((t + 1) < T_) && (((t + 1) & 31) == 0);
        float ginext = 0.0f;
        if ((t + 1 < T_) && !newchunk)
            ginext = __ldcg(&gi[((size_t)(t + 1) * B_ + b) * G_ + g]) + bi;

        unsigned long long acc0 = pk2(bh, 0.0f);
        unsigned long long acc1 = z64, acc2 = z64, acc3 = z64;
        const ulonglong2* hq = (const ulonglong2*)h_sh;
#pragma unroll
        for (int i = 0; i < 16; i++) {
            ulonglong2 hv0 = hq[2 * i + 0];
            ulonglong2 hv1 = hq[2 * i + 1];
            acc0 = fma2(w2[4 * i + 0], hv0.x, acc0);
            acc1 = fma2(w2[4 * i + 1], hv0.y, acc1);
            acc2 = fma2(w2[4 * i + 2], hv1.x, acc2);
            acc3 = fma2(w2[4 * i + 3], hv1.y, acc3);
        }
        float a0, a1, a2, a3, a4, a5, a6, a7;
        upk2(acc0, a0, a1); upk2(acc1, a2, a3);
        upk2(acc2, a4, a5); upk2(acc3, a6, a7);
        float ghval = ((a0 + a2) + (a1 + a3)) + ((a4 + a6) + (a5 + a7));

        if (grp == 0) r_sh[j] = sigm(gic + ghval);
        else if (grp == 1) z_sh[j] = sigm(gic + ghval);
        __syncthreads();   // bar A

        if (grp == 2) {
            float n  = tanh_fast(gic + r_sh[j] * ghval);
            float z  = z_sh[j];
            float hn = (1.0f - z) * n + z * h_sh[j];
            h_sh[j] = hn;
            out_f32[((size_t)b * T_ + t) * H_ + j] = hn;
        }
        __syncthreads();   // bar B

        if (newchunk) {
            if (g == 0)
                while (*(volatile int*)&g_gcnt1[(t + 1) >> 5] < TILES_PER_CHUNK)
                    __nanosleep(128);
            __syncthreads();
            gic = __ldcg(&gi[((size_t)(t + 1) * B_ + b) * G_ + g]) + bi;
        } else {
            gic = ginext;
        }
    }
}

// ---- GEMM1 worker body: gi1 tiles 128(M) x 96(N), 12 warps, 32x32 warp tiles
static __device__ __forceinline__ void worker_gemm(
    char* dsm,
    const __nv_bfloat16* __restrict__ a_hi,   // hseq hi [M_,128]
    const __nv_bfloat16* __restrict__ a_lo,
    const __nv_bfloat16* __restrict__ w_hi,   // w1 hi [384,128]
    const __nv_bfloat16* __restrict__ w_lo,
    float* __restrict__ Cout)                 // gi1 [M_,384]
{
    __nv_bfloat16* Ahi = (__nv_bfloat16*)(dsm + WSM_AHI);
    __nv_bfloat16* Alo = (__nv_bfloat16*)(dsm + WSM_ALO);
    __nv_bfloat16* Whi = (__nv_bfloat16*)(dsm + WSM_WHI);
    __nv_bfloat16* Wlo = (__nv_bfloat16*)(dsm + WSM_WLO);
    __shared__ int sh_tile;

    const int tid = threadIdx.x;
    const int w   = tid >> 5;
    const int wr  = w / 3;        // 0..3 -> M offset wr*32
    const int wc  = w % 3;        // 0..2 -> N offset wc*32

    for (;;) {
        if (tid == 0) sh_tile = atomicAdd(&g_ticket, 1);
        __syncthreads();
        int tile = sh_tile;
        if (tile >= NTILES) break;
        int mt = tile >> 2;              // m-tile 0..1023
        int nt = tile & 3;               // n-tile 0..3
        int bm = mt * 128;
        int bn = nt * 96;
        int chunk = mt >> 4;             // timesteps 2mt..2mt+1 -> chunk mt/16

        if (tid == 0)
            while (*(volatile int*)&g_cnt0[chunk] < B_) __nanosleep(128);
        __syncthreads();

        // load A (128 rows) and W (96 rows), 16B chunks, LDM=136
        for (int i = tid; i < 128 * 16; i += 384) {
            int row = i >> 4, ch = i & 15;
            const uint4* ph = (const uint4*)(a_hi + (size_t)(bm + row) * H_) + ch;
            const uint4* pl = (const uint4*)(a_lo + (size_t)(bm + row) * H_) + ch;
            size_t doff = (size_t)row * LDM + ch * 8;
            *(uint4*)(Ahi + doff) = __ldcg(ph);
            *(uint4*)(Alo + doff) = __ldcg(pl);
        }
        for (int i = tid; i < 96 * 16; i += 384) {
            int row = i >> 4, ch = i & 15;
            size_t doff = (size_t)row * LDM + ch * 8;
            *(uint4*)(Whi + doff) = *((const uint4*)(w_hi + (size_t)(bn + row) * H_) + ch);
            *(uint4*)(Wlo + doff) = *((const uint4*)(w_lo + (size_t)(bn + row) * H_) + ch);
        }
        __syncthreads();

        wmma::fragment<wmma::accumulator, 16, 16, 16, float> acc[2][2];
#pragma unroll
        for (int i = 0; i < 2; i++)
#pragma unroll
            for (int j = 0; j < 2; j++) wmma::fill_fragment(acc[i][j], 0.0f);

#pragma unroll
        for (int kc = 0; kc < 8; kc++) {
            int k0 = kc * 16;
            wmma::fragment<wmma::matrix_a, 16, 16, 16, __nv_bfloat16, wmma::row_major> fah[2], fal[2];
            wmma::fragment<wmma::matrix_b, 16, 16, 16, __nv_bfloat16, wmma::col_major> fwh[2], fwl[2];
#pragma unroll
            for (int i = 0; i < 2; i++) {
                int m0 = wr * 32 + i * 16;
                wmma::load_matrix_sync(fah[i], Ahi + (size_t)m0 * LDM + k0, LDM);
                wmma::load_matrix_sync(fal[i], Alo + (size_t)m0 * LDM + k0, LDM);
            }
#pragma unroll
            for (int j = 0; j < 2; j++) {
                int n0 = wc * 32 + j * 16;
                wmma::load_matrix_sync(fwh[j], Whi + (size_t)n0 * LDM + k0, LDM);
                wmma::load_matrix_sync(fwl[j], Wlo + (size_t)n0 * LDM + k0, LDM);
            }
#pragma unroll
            for (int i = 0; i < 2; i++)
#pragma unroll
                for (int j = 0; j < 2; j++) {
                    wmma::mma_sync(acc[i][j], fah[i], fwh[j], acc[i][j]);
                    wmma::mma_sync(acc[i][j], fah[i], fwl[j], acc[i][j]);
                    wmma::mma_sync(acc[i][j], fal[i], fwh[j], acc[i][j]);
                }
        }

#pragma unroll
        for (int i = 0; i < 2; i++) {
            int m = bm + wr * 32 + i * 16;
#pragma unroll
            for (int j = 0; j < 2; j++) {
                int n = bn + wc * 32 + j * 16;
                wmma::store_matrix_sync(Cout + (size_t)m * G_ + n, acc[i][j], G_,
                                        wmma::mem_row_major);
            }
        }
        __threadfence();      // release gi1 stores
        __syncthreads();
        if (tid == 0) atomicAdd(&g_gcnt1[chunk], 1);
    }
}

__global__ __launch_bounds__(384, 1) void fused_kernel(
    const float* __restrict__ gi0,
    const float* __restrict__ whh0, const float* __restrict__ bih0,
    const float* __restrict__ bhh0,
    const float* __restrict__ whh1, const float* __restrict__ bih1,
    const float* __restrict__ bhh1,
    float* __restrict__ gi1,
    __nv_bfloat16* __restrict__ hhi, __nv_bfloat16* __restrict__ hlo,
    const __nv_bfloat16* __restrict__ w1h, const __nv_bfloat16* __restrict__ w1l,
    float* __restrict__ y)
{
    extern __shared__ __align__(16) char dsm[];
    const int bid = blockIdx.x;
    if (bid < 64) {
        scan_l0(dsm, bid, gi0, whh0, bih0, bhh0, hhi, hlo);
    } else if (bid < 128) {
        scan_l1(dsm, bid - 64, gi1, whh1, bih1, bhh1, y);
    } else {
        worker_gemm(dsm, hhi, hlo, w1h, w1l, gi1);
    }
}

// ---------------- FC: out[M,32] = relu(Y[M,128] @ fcw[32,128]^T + fcb) -----
__global__ __launch_bounds__(256) void fc_kernel(
    const float* __restrict__ Y,
    const float* __restrict__ fcw,
    const float* __restrict__ fcb,
    float*       __restrict__ out)
{
    __shared__ float Wt[128][33];
    __shared__ float As[128][33];

    const int bm  = blockIdx.x * 32;
    const int tid = threadIdx.x;

#pragma unroll
    for (int j = 0; j < 4; j++) {
        int f  = tid + j * 256;
        int c  = f >> 5;
        int kq = f & 31;
        float4 v = *(const float4*)(fcw + (size_t)c * 128 + kq * 4);
        Wt[kq * 4 + 0][c] = v.x;
        Wt[kq * 4 + 1][c] = v.y;
        Wt[kq * 4 + 2][c] = v.z;
        Wt[kq * 4 + 3][c] = v.w;
    }
#pragma unroll
    for (int j = 0; j < 4; j++) {
        int f  = tid + j * 256;
        int r  = f >> 5;
        int kq = f & 31;
        float4 v = *(const float4*)(Y + (size_t)(bm + r) * 128 + kq * 4);
        As[kq * 4 + 0][r] = v.x;
        As[kq * 4 + 1][r] = v.y;
        As[kq * 4 + 2][r] = v.z;
        As[kq * 4 + 3][r] = v.w;
    }
    __syncthreads();

    const int c  = tid & 31;
    const int rg = tid >> 5;
    float acc[4] = {0.f, 0.f, 0.f, 0.f};
#pragma unroll
    for (int k = 0; k < 128; k++) {
        float w = Wt[k][c];
#pragma unroll
        for (int i = 0; i < 4; i++) acc[i] += As[k][rg * 4 + i] * w;
    }
    float bb = fcb[c];
#pragma unroll
    for (int i = 0; i < 4; i++) {
        float v = acc[i] + bb;
        out[(size_t)(bm + rg * 4 + i) * C_ + c] = fmaxf(v, 0.0f);
    }
}

// ---------------- launch ----------------------------------------------------
extern "C" void kernel_launch(void* const* d_in, const int* in_sizes, int n_in,
                              void* d_out, int out_size)
{
    const int*   x    = (const int*)  d_in[0];
    const float* emb  = (const float*)d_in[1];
    const float* wih0 = (const float*)d_in[2];
    const float* whh0 = (const float*)d_in[3];
    const float* bih0 = (const float*)d_in[4];
    const float* bhh0 = (const float*)d_in[5];
    const float* wih1 = (const float*)d_in[6];
    const float* whh1 = (const float*)d_in[7];
    const float* bih1 = (const float*)d_in[8];
    const float* bhh1 = (const float*)d_in[9];
    const float* fcw  = (const float*)d_in[10];
    const float* fcb  = (const float*)d_in[11];
    float* out = (float*)d_out;

    void* p;
    cudaGetSymbolAddress(&p, g_gi0);     float* gi0  = (float*)p;
    cudaGetSymbolAddress(&p, g_gi1);     float* gi1  = (float*)p;
    cudaGetSymbolAddress(&p, g_y);       float* y    = (float*)p;
    cudaGetSymbolAddress(&p, g_hseq_hi); __nv_bfloat16* hhi = (__nv_bfloat16*)p;
    cudaGetSymbolAddress(&p, g_hseq_lo); __nv_bfloat16* hlo = (__nv_bfloat16*)p;
    cudaGetSymbolAddress(&p, g_emb_hi);  __nv_bfloat16* ehi = (__nv_bfloat16*)p;
    cudaGetSymbolAddress(&p, g_emb_lo);  __nv_bfloat16* elo = (__nv_bfloat16*)p;
    cudaGetSymbolAddress(&p, g_w0_hi);   __nv_bfloat16* w0h = (__nv_bfloat16*)p;
    cudaGetSymbolAddress(&p, g_w0_lo);   __nv_bfloat16* w0l = (__nv_bfloat16*)p;
    cudaGetSymbolAddress(&p, g_w1_hi);   __nv_bfloat16* w1h = (__nv_bfloat16*)p;
    cudaGetSymbolAddress(&p, g_w1_lo);   __nv_bfloat16* w1l = (__nv_bfloat16*)p;

    cudaFuncSetAttribute(gemm_wmma, cudaFuncAttributeMaxDynamicSharedMemorySize, SM_TOT);
    cudaFuncSetAttribute(fused_kernel, cudaFuncAttributeMaxDynamicSharedMemorySize, WSM_TOT);

    // 0) split emb + input-gate weights into bf16 hi/lo
    long nconv = (long)V_ * H_ + 2L * G_ * H_;
    convert_kernel<<<(unsigned)((nconv + 255) / 256), 256>>>(emb, wih0, wih1);

    // 1) gi0 = gather(emb, x) @ w_ih0^T (full chip)
    dim3 ggrid(G_ / 128, M_ / 128);
    gemm_wmma<<<ggrid, 256, SM_TOT>>>(x, ehi, elo, w0h, w0l, gi0);

    // 2) reset pipeline flags (each replay)
    zero_flags<<<1, 64>>>();

    // 3) fused: L0 scan (64 CTAs) | gi1 GEMM workers (20 CTAs) | L1 scan (64 CTAs)
    fused_kernel<<<148, 384, WSM_TOT>>>(gi0, whh0, bih0, bhh0,
                                        whh1, bih1, bhh1,
                                        gi1, hhi, hlo, w1h, w1l, y);

    // 4) out = relu(y @ fc_w^T + fc_b)
    fc_kernel<<<M_ / 32, 256>>>(y, fcw, fcb, out);
}